// round 11
// baseline (speedup 1.0000x reference)
#include <cuda_runtime.h>
#include <cuda.h>
#include <cuda_bf16.h>

// PointPillars BEV scatter, inverted as a gather with TMA tensor stores.
//   1) cudaMemsetAsync grid to 0xFF (-1)
//   2) scatter pillar ids into grid[(b*H+y)*W+x]
//   3) persistent gather blocks (3/SM): per-cell branchy feature gather
//      (strided channels, 64B-coalesced), STS into SW128-swizzled TMA-box
//      layout, cp.async.bulk.tensor.4d stores (4 x 8KB per tile) issued by
//      one thread. Double-buffered; wait_group.read gates smem reuse.
#define BEV_H 496
#define BEV_W 432
#define BB    4
#define CC    64
#define GRID_CELLS (BB * BEV_H * BEV_W)   // 857088
#define TILE_X 128
#define NT     (BB * BEV_H * 4)           // 7936 tiles
#define SUB_FLOATS 2048                    // one TMA box: 32 x * 64 c floats (8KB)
#define TILE_FLOATS (4 * SUB_FLOATS)       // 8192 floats = 32KB
#define GATHER_BLOCKS 456                  // 3 per SM on 152-SM GB300
#define SMEM_BYTES (2 * TILE_FLOATS * 4 + 1024)  // 2 buffers + align slack

__device__ int g_grid[GRID_CELLS];

__global__ void scatter_ids_kernel(const int* __restrict__ coords, int M) {
    int m = blockIdx.x * blockDim.x + threadIdx.x;
    if (m < M) {
        int b = coords[3 * m + 0];
        int y = coords[3 * m + 1];
        int x = coords[3 * m + 2];
        g_grid[(b * BEV_H + y) * BEV_W + x] = m;
    }
}

__global__ __launch_bounds__(512, 3) void gather_kernel(
    const float* __restrict__ feat, float* __restrict__ out,
    const __grid_constant__ CUtensorMap tmap)
{
    extern __shared__ float smem_raw[];
    uint32_t sbase_u = (uint32_t)__cvta_generic_to_shared(smem_raw);
    uint32_t sbuf_u  = (sbase_u + 1023u) & ~1023u;          // 1KB align for SW128
    float*   buf     = (float*)((char*)smem_raw + (sbuf_u - sbase_u));

    const int tid   = threadIdx.x;
    const int p     = tid & 15;                  // channel lane (0..15)
    const int rbase = tid >> 4;                  // x within subtile (0..31)
    const int rx    = rbase ^ ((p & 7) << 2);    // SW128 in-row swizzle

    const int step = gridDim.x;
    const int t0   = blockIdx.x;

    // ---- per-thread idx loads (lanes broadcast from L1) ----
    auto load_idx = [&](int t, int* dst) {
#pragma unroll
        for (int i = 0; i < 4; i++) {
            int r = t >> 2;
            int x = (t & 3) * TILE_X + i * 32 + rbase;
            dst[i] = (x < BEV_W) ? __ldg(&g_grid[r * BEV_W + x]) : -1;
        }
    };

    // ---- branchy gather, strided channels c = p + 16j (64B coalesced) ----
    auto gather = [&](const int* idx, float* v) {
#pragma unroll
        for (int i = 0; i < 4; i++) {
#pragma unroll
            for (int j = 0; j < 4; j++) {
                float w = 0.f;
                if (idx[i] >= 0)
                    w = __ldg(feat + (size_t)idx[i] * CC + p + 16 * j);
                v[4 * i + j] = w;
            }
        }
    };

    int   idx_n[4], idx_p[4];
    float v[16];

    // ---- prologue ----
    {
        int idx_c[4];
        load_idx(t0, idx_c);
        gather(idx_c, v);
    }
    if (t0 + step < NT) load_idx(t0 + step, idx_n);

    int k = 0;
    for (int t = t0; t < NT; t += step, k++) {
        float* wb = buf + (size_t)(k & 1) * TILE_FLOATS;

        // Stage 1: STS tile t into SW128-swizzled TMA box layout
        // (row = channel, 128B rows; ~2-way bank conflicts).
#pragma unroll
        for (int i = 0; i < 4; i++) {
#pragma unroll
            for (int j = 0; j < 4; j++) {
                wb[i * SUB_FLOATS + (p + 16 * j) * 32 + rx] = v[4 * i + j];
            }
        }

        // Prefetch idx 2 tiles ahead; gather features for next tile
        // (LDGs in flight across barrier + TMA issue).
        if (t + 2 * step < NT) load_idx(t + 2 * step, idx_p);
        if (t + step < NT)     gather(idx_n, v);

        // order generic-proxy STS before async-proxy TMA reads
        asm volatile("fence.proxy.async.shared::cta;" ::: "memory");
        __syncthreads();

        if (tid == 0) {
            int r  = t >> 2;
            int b  = r / BEV_H;
            int y  = r - b * BEV_H;
            int xb = (t & 3) * TILE_X;
            uint32_t sa = sbuf_u + (uint32_t)(k & 1) * (TILE_FLOATS * 4);
            int zero = 0;
#pragma unroll
            for (int s = 0; s < 4; s++) {
                int x0 = xb + 32 * s;
                if (x0 < BEV_W) {  // OOB columns inside a box are clamped by TMA
                    asm volatile(
                        "cp.async.bulk.tensor.4d.global.shared::cta.tile.bulk_group "
                        "[%0, {%1, %2, %3, %4}], [%5];"
                        :: "l"(&tmap), "r"(x0), "r"(y), "r"(zero), "r"(b),
                           "r"(sa + (uint32_t)s * (SUB_FLOATS * 4))
                        : "memory");
                }
            }
            asm volatile("cp.async.bulk.commit_group;" ::: "memory");
            // group k just committed may stay in flight; group k-1's smem
            // reads must be done before next iter overwrites its buffer.
            asm volatile("cp.async.bulk.wait_group.read 1;" ::: "memory");
        }
        __syncthreads();

#pragma unroll
        for (int i = 0; i < 4; i++) idx_n[i] = idx_p[i];
    }

    if (tid == 0) {
        asm volatile("cp.async.bulk.wait_group 0;" ::: "memory");
    }
}

typedef CUresult (*PFN_encodeTiled)(
    CUtensorMap*, CUtensorMapDataType, cuuint32_t, void*,
    const cuuint64_t*, const cuuint64_t*, const cuuint32_t*, const cuuint32_t*,
    CUtensorMapInterleave, CUtensorMapSwizzle, CUtensorMapL2promotion,
    CUtensorMapFloatOOBfill);

extern "C" void kernel_launch(void* const* d_in, const int* in_sizes, int n_in,
                              void* d_out, int out_size)
{
    const int*   coords = (const int*)d_in[0];    // (M, 3) int32 [b, y, x]
    const float* feat   = (const float*)d_in[1];  // (M, 64) float32
    float*       out    = (float*)d_out;          // (4, 64, 496, 432) float32

    const int M = in_sizes[0] / 3;

    // Tensor map for the output, dims ordered by stride: (x, y, c, b).
    // Box (32,1,64,1): 32 floats = 128B rows, 64 channel rows, SW128 swizzle.
    PFN_encodeTiled encode = nullptr;
    cudaDriverEntryPointQueryResult qres;
    cudaGetDriverEntryPoint("cuTensorMapEncodeTiled", (void**)&encode,
                            cudaEnableDefault, &qres);
    CUtensorMap tmap;
    {
        cuuint64_t dims[4]    = {BEV_W, BEV_H, CC, BB};
        cuuint64_t strides[3] = {
            (cuuint64_t)BEV_W * 4,
            (cuuint64_t)BEV_H * BEV_W * 4,
            (cuuint64_t)CC * BEV_H * BEV_W * 4};
        cuuint32_t box[4] = {32, 1, 64, 1};
        cuuint32_t es[4]  = {1, 1, 1, 1};
        encode(&tmap, CU_TENSOR_MAP_DATA_TYPE_FLOAT32, 4, d_out,
               dims, strides, box, es,
               CU_TENSOR_MAP_INTERLEAVE_NONE, CU_TENSOR_MAP_SWIZZLE_128B,
               CU_TENSOR_MAP_L2_PROMOTION_L2_128B,
               CU_TENSOR_MAP_FLOAT_OOB_FILL_NONE);
    }

    void* grid_ptr = nullptr;
    cudaGetSymbolAddress(&grid_ptr, g_grid);
    cudaMemsetAsync(grid_ptr, 0xFF, GRID_CELLS * sizeof(int));  // all cells = -1

    scatter_ids_kernel<<<(M + 255) / 256, 256>>>(coords, M);

    cudaFuncSetAttribute(gather_kernel,
                         cudaFuncAttributeMaxDynamicSharedMemorySize, SMEM_BYTES);
    gather_kernel<<<GATHER_BLOCKS, 512, SMEM_BYTES>>>(feat, out, tmap);
}

// round 13
// speedup vs baseline: 1.0057x; 1.0057x over previous
#include <cuda_runtime.h>
#include <cuda.h>
#include <cuda_bf16.h>

// PointPillars BEV scatter, inverted as a gather with TMA tensor stores.
//   1) cudaMemsetAsync grid to 0xFF (-1)
//   2) scatter pillar ids into grid[(b*H+y)*W+x]
//   3) persistent gather blocks (3/SM): per-cell branchy feature gather
//      (strided channels, 64B-coalesced), STS into SW128-swizzled TMA-box
//      layout, cp.async.bulk.tensor.4d stores. The 4 boxes per tile are
//      issued by lane 0 of warps 0..3 (parallel bulk-group chains), not one
//      serialized thread. Double-buffered; wait_group.read gates smem reuse.
#define BEV_H 496
#define BEV_W 432
#define BB    4
#define CC    64
#define GRID_CELLS (BB * BEV_H * BEV_W)   // 857088
#define TILE_X 128
#define NT     (BB * BEV_H * 4)           // 7936 tiles
#define SUB_FLOATS 2048                    // one TMA box: 32 x * 64 c floats (8KB)
#define TILE_FLOATS (4 * SUB_FLOATS)       // 8192 floats = 32KB
#define GATHER_BLOCKS 456                  // 3 per SM on 152-SM GB300
#define SMEM_BYTES (2 * TILE_FLOATS * 4 + 1024)  // 2 buffers + align slack

__device__ int g_grid[GRID_CELLS];

__global__ void scatter_ids_kernel(const int* __restrict__ coords, int M) {
    int m = blockIdx.x * blockDim.x + threadIdx.x;
    if (m < M) {
        int b = coords[3 * m + 0];
        int y = coords[3 * m + 1];
        int x = coords[3 * m + 2];
        g_grid[(b * BEV_H + y) * BEV_W + x] = m;
    }
}

__global__ __launch_bounds__(512, 3) void gather_kernel(
    const float* __restrict__ feat, float* __restrict__ out,
    const __grid_constant__ CUtensorMap tmap)
{
    extern __shared__ float smem_raw[];
    uint32_t sbase_u = (uint32_t)__cvta_generic_to_shared(smem_raw);
    uint32_t sbuf_u  = (sbase_u + 1023u) & ~1023u;          // 1KB align for SW128
    float*   buf     = (float*)((char*)smem_raw + (sbuf_u - sbase_u));

    const int tid   = threadIdx.x;
    const int p     = tid & 15;                  // channel lane (0..15)
    const int rbase = tid >> 4;                  // x within subtile (0..31)
    const int rx    = rbase ^ ((p & 7) << 2);    // SW128 in-row swizzle

    const int step = gridDim.x;
    const int t0   = blockIdx.x;

    // ---- per-thread idx loads (lanes broadcast from L1) ----
    auto load_idx = [&](int t, int* dst) {
#pragma unroll
        for (int i = 0; i < 4; i++) {
            int r = t >> 2;
            int x = (t & 3) * TILE_X + i * 32 + rbase;
            dst[i] = (x < BEV_W) ? __ldg(&g_grid[r * BEV_W + x]) : -1;
        }
    };

    // ---- branchy gather, strided channels c = p + 16j (64B coalesced) ----
    auto gather = [&](const int* idx, float* v) {
#pragma unroll
        for (int i = 0; i < 4; i++) {
#pragma unroll
            for (int j = 0; j < 4; j++) {
                float w = 0.f;
                if (idx[i] >= 0)
                    w = __ldg(feat + (size_t)idx[i] * CC + p + 16 * j);
                v[4 * i + j] = w;
            }
        }
    };

    int   idx_n[4], idx_p[4];
    float v[16];

    // ---- prologue ----
    {
        int idx_c[4];
        load_idx(t0, idx_c);
        gather(idx_c, v);
    }
    if (t0 + step < NT) load_idx(t0 + step, idx_n);

    const bool issuer = (tid < 128) && ((tid & 31) == 0);  // lane 0 of warps 0..3
    const int  sbox   = tid >> 5;                          // box id for issuers

    int k = 0;
    for (int t = t0; t < NT; t += step, k++) {
        float* wb = buf + (size_t)(k & 1) * TILE_FLOATS;

        // Stage 1: STS tile t into SW128-swizzled TMA box layout
        // (row = channel, 128B rows; 2-way bank conflicts).
#pragma unroll
        for (int i = 0; i < 4; i++) {
#pragma unroll
            for (int j = 0; j < 4; j++) {
                wb[i * SUB_FLOATS + (p + 16 * j) * 32 + rx] = v[4 * i + j];
            }
        }

        // Prefetch idx 2 tiles ahead; gather features for next tile
        // (LDGs in flight across barrier + TMA issue).
        if (t + 2 * step < NT) load_idx(t + 2 * step, idx_p);
        if (t + step < NT)     gather(idx_n, v);

        // order generic-proxy STS before async-proxy TMA reads
        asm volatile("fence.proxy.async.shared::cta;" ::: "memory");
        __syncthreads();

        if (issuer) {
            int r  = t >> 2;
            int b  = r / BEV_H;
            int y  = r - b * BEV_H;
            int x0 = (t & 3) * TILE_X + 32 * sbox;
            uint32_t sa = sbuf_u + (uint32_t)(k & 1) * (TILE_FLOATS * 4)
                                 + (uint32_t)sbox * (SUB_FLOATS * 4);
            int zero = 0;
            if (x0 < BEV_W) {
                asm volatile(
                    "cp.async.bulk.tensor.4d.global.shared::cta.tile.bulk_group "
                    "[%0, {%1, %2, %3, %4}], [%5];"
                    :: "l"(&tmap), "r"(x0), "r"(y), "r"(zero), "r"(b), "r"(sa)
                    : "memory");
            }
            asm volatile("cp.async.bulk.commit_group;" ::: "memory");
            // this issuer's group from tile k-2 must have finished READING its
            // smem before the next iteration overwrites that buffer.
            asm volatile("cp.async.bulk.wait_group.read 1;" ::: "memory");
        }
        __syncthreads();

#pragma unroll
        for (int i = 0; i < 4; i++) idx_n[i] = idx_p[i];
    }

    if (issuer) {
        asm volatile("cp.async.bulk.wait_group 0;" ::: "memory");
    }
}

typedef CUresult (*PFN_encodeTiled)(
    CUtensorMap*, CUtensorMapDataType, cuuint32_t, void*,
    const cuuint64_t*, const cuuint64_t*, const cuuint32_t*, const cuuint32_t*,
    CUtensorMapInterleave, CUtensorMapSwizzle, CUtensorMapL2promotion,
    CUtensorMapFloatOOBfill);

extern "C" void kernel_launch(void* const* d_in, const int* in_sizes, int n_in,
                              void* d_out, int out_size)
{
    const int*   coords = (const int*)d_in[0];    // (M, 3) int32 [b, y, x]
    const float* feat   = (const float*)d_in[1];  // (M, 64) float32
    float*       out    = (float*)d_out;          // (4, 64, 496, 432) float32

    const int M = in_sizes[0] / 3;

    // Tensor map for the output, dims ordered by stride: (x, y, c, b).
    // Box (32,1,64,1): 32 floats = 128B rows, 64 channel rows, SW128 swizzle.
    PFN_encodeTiled encode = nullptr;
    cudaDriverEntryPointQueryResult qres;
    cudaGetDriverEntryPoint("cuTensorMapEncodeTiled", (void**)&encode,
                            cudaEnableDefault, &qres);
    CUtensorMap tmap;
    {
        cuuint64_t dims[4]    = {BEV_W, BEV_H, CC, BB};
        cuuint64_t strides[3] = {
            (cuuint64_t)BEV_W * 4,
            (cuuint64_t)BEV_H * BEV_W * 4,
            (cuuint64_t)CC * BEV_H * BEV_W * 4};
        cuuint32_t box[4] = {32, 1, 64, 1};
        cuuint32_t es[4]  = {1, 1, 1, 1};
        encode(&tmap, CU_TENSOR_MAP_DATA_TYPE_FLOAT32, 4, d_out,
               dims, strides, box, es,
               CU_TENSOR_MAP_INTERLEAVE_NONE, CU_TENSOR_MAP_SWIZZLE_128B,
               CU_TENSOR_MAP_L2_PROMOTION_L2_128B,
               CU_TENSOR_MAP_FLOAT_OOB_FILL_NONE);
    }

    void* grid_ptr = nullptr;
    cudaGetSymbolAddress(&grid_ptr, g_grid);
    cudaMemsetAsync(grid_ptr, 0xFF, GRID_CELLS * sizeof(int));  // all cells = -1

    scatter_ids_kernel<<<(M + 255) / 256, 256>>>(coords, M);

    cudaFuncSetAttribute(gather_kernel,
                         cudaFuncAttributeMaxDynamicSharedMemorySize, SMEM_BYTES);
    gather_kernel<<<GATHER_BLOCKS, 512, SMEM_BYTES>>>(feat, out, tmap);
}